// round 7
// baseline (speedup 1.0000x reference)
#include <cuda_runtime.h>
#include <cuda_bf16.h>
#include <math.h>

// Problem dims (fixed by reference setup_inputs)
constexpr int Bc = 32;
constexpr int Tc = 4;
constexpr int Lc = 196;
constexpr int Dc = 384;
constexpr int Hc = 1536;
constexpr int Mrows = Tc * Bc * Lc;   // 25088

// Scratch (device globals; allocation-free per harness rules)
__device__ float g_h1[(size_t)Mrows * Hc];   // pre-LN GEMM1 output  (~154 MB)
__device__ float g_s1[(size_t)Mrows * Hc];   // spikes layer 1       (~154 MB)
__device__ float g_h2[(size_t)Mrows * Dc];   // pre-LN GEMM2 output  (~38 MB)

// ---------------------------------------------------------------------------
// GEMM core: 128x128 tile, BK=16, 256 threads, 8x8 per thread (split 4+4,
// conflict-free), double-buffered, 1 sync per 16-k iter, 2 CTAs/SM.
// Bit-exactness contract: each output element is ONE fp32 FMA chain with k
// strictly ascending 0..K-1 (matches the reference einsum), bias added as a
// single separate __fadd_rn at the end.
// blockIdx.x = N-block (small), blockIdx.y = M-block  -> consecutive CTAs
// share the A block and the whole weight matrix through L2.
// Smem rows padded 128->132 floats (132 % 32 == 4) -> conflict-free STS.
// ---------------------------------------------------------------------------
#define GEMM_BODY(K_DIM, APTR_EXPR, BPTR_EXPR, BIAS, OUTBASE, OUT_LD)          \
    constexpr int BK = 16;                                                     \
    constexpr int LDS_ = 132;                                                  \
    __shared__ float As[2][BK][LDS_];                                          \
    __shared__ float Bs[2][BK][LDS_];                                          \
    const int tid = threadIdx.x;                                               \
    const int lr = tid >> 1;                                                   \
    const int lc = (tid & 1) * 8;                                              \
    const float* aptr = (APTR_EXPR);                                           \
    const float* bptr = (BPTR_EXPR);                                           \
    const int tx = tid & 15;                                                   \
    const int ty = tid >> 4;                                                   \
    float acc[8][8] = {};                                                      \
    float4 av0 = *(const float4*)aptr;                                         \
    float4 av1 = *(const float4*)(aptr + 4);                                   \
    float4 bv0 = *(const float4*)bptr;                                         \
    float4 bv1 = *(const float4*)(bptr + 4);                                   \
    int buf = 0;                                                               \
    As[0][lc + 0][lr] = av0.x; As[0][lc + 1][lr] = av0.y;                      \
    As[0][lc + 2][lr] = av0.z; As[0][lc + 3][lr] = av0.w;                      \
    As[0][lc + 4][lr] = av1.x; As[0][lc + 5][lr] = av1.y;                      \
    As[0][lc + 6][lr] = av1.z; As[0][lc + 7][lr] = av1.w;                      \
    Bs[0][lc + 0][lr] = bv0.x; Bs[0][lc + 1][lr] = bv0.y;                      \
    Bs[0][lc + 2][lr] = bv0.z; Bs[0][lc + 3][lr] = bv0.w;                      \
    Bs[0][lc + 4][lr] = bv1.x; Bs[0][lc + 5][lr] = bv1.y;                      \
    Bs[0][lc + 6][lr] = bv1.z; Bs[0][lc + 7][lr] = bv1.w;                      \
    __syncthreads();                                                           \
    for (int k0 = BK; k0 < (K_DIM) + BK; k0 += BK) {                           \
        const bool more = (k0 < (K_DIM));                                      \
        if (more) {                                                            \
            av0 = *(const float4*)(aptr + k0);                                 \
            av1 = *(const float4*)(aptr + k0 + 4);                             \
            bv0 = *(const float4*)(bptr + k0);                                 \
            bv1 = *(const float4*)(bptr + k0 + 4);                             \
        }                                                                      \
        _Pragma("unroll")                                                      \
        for (int k = 0; k < BK; k++) {                                         \
            const float4 a0 = *(const float4*)&As[buf][k][ty * 4];             \
            const float4 a1 = *(const float4*)&As[buf][k][64 + ty * 4];        \
            const float4 b0 = *(const float4*)&Bs[buf][k][tx * 4];             \
            const float4 b1 = *(const float4*)&Bs[buf][k][64 + tx * 4];        \
            const float am[8] = {a0.x, a0.y, a0.z, a0.w, a1.x, a1.y, a1.z, a1.w}; \
            const float bn[8] = {b0.x, b0.y, b0.z, b0.w, b1.x, b1.y, b1.z, b1.w}; \
            _Pragma("unroll")                                                  \
            for (int i = 0; i < 8; i++) {                                      \
                _Pragma("unroll")                                              \
                for (int j = 0; j < 8; j++)                                    \
                    acc[i][j] = __fmaf_rn(am[i], bn[j], acc[i][j]);            \
            }                                                                  \
        }                                                                      \
        if (more) {                                                            \
            buf ^= 1;                                                          \
            As[buf][lc + 0][lr] = av0.x; As[buf][lc + 1][lr] = av0.y;          \
            As[buf][lc + 2][lr] = av0.z; As[buf][lc + 3][lr] = av0.w;          \
            As[buf][lc + 4][lr] = av1.x; As[buf][lc + 5][lr] = av1.y;          \
            As[buf][lc + 6][lr] = av1.z; As[buf][lc + 7][lr] = av1.w;          \
            Bs[buf][lc + 0][lr] = bv0.x; Bs[buf][lc + 1][lr] = bv0.y;          \
            Bs[buf][lc + 2][lr] = bv0.z; Bs[buf][lc + 3][lr] = bv0.w;          \
            Bs[buf][lc + 4][lr] = bv1.x; Bs[buf][lc + 5][lr] = bv1.y;          \
            Bs[buf][lc + 6][lr] = bv1.z; Bs[buf][lc + 7][lr] = bv1.w;          \
            __syncthreads();                                                   \
        }                                                                      \
    }                                                                          \
    const int n_base = blockIdx.x * 128;                                       \
    const int m_base = blockIdx.y * 128;                                       \
    const float4 bb0 = *(const float4*)((BIAS) + n_base + tx * 4);             \
    const float4 bb1 = *(const float4*)((BIAS) + n_base + 64 + tx * 4);        \
    _Pragma("unroll")                                                          \
    for (int i = 0; i < 8; i++) {                                              \
        const int m = m_base + ((i < 4) ? (ty * 4 + i) : (64 + ty * 4 + i - 4)); \
        float* o = (OUTBASE) + (size_t)m * (OUT_LD) + n_base;                  \
        float4 o0, o1;                                                         \
        o0.x = __fadd_rn(acc[i][0], bb0.x); o0.y = __fadd_rn(acc[i][1], bb0.y);\
        o0.z = __fadd_rn(acc[i][2], bb0.z); o0.w = __fadd_rn(acc[i][3], bb0.w);\
        o1.x = __fadd_rn(acc[i][4], bb1.x); o1.y = __fadd_rn(acc[i][5], bb1.y);\
        o1.z = __fadd_rn(acc[i][6], bb1.z); o1.w = __fadd_rn(acc[i][7], bb1.w);\
        *(float4*)(o + tx * 4) = o0;                                           \
        *(float4*)(o + 64 + tx * 4) = o1;                                      \
    }

__global__ __launch_bounds__(256, 2) void gemm1_kernel(
    const float* __restrict__ x, const float* __restrict__ W1,
    const float* __restrict__ b1) {
    // A row r = (t*B + b)*L + l maps into x at ((b*T + t)*L + l)*D
    const int r_ = blockIdx.y * 128 + (threadIdx.x >> 1);
    const int l_  = r_ % Lc;
    const int tb_ = r_ / Lc;
    const int bI_ = tb_ % Bc;
    const int tI_ = tb_ / Bc;
    GEMM_BODY(Dc,
              x  + (size_t)((bI_ * Tc + tI_) * Lc + l_) * Dc + ((threadIdx.x & 1) * 8),
              W1 + (size_t)(blockIdx.x * 128 + (threadIdx.x >> 1)) * Dc + ((threadIdx.x & 1) * 8),
              b1, g_h1, Hc)
}

__global__ __launch_bounds__(256, 2) void gemm2_kernel(
    const float* __restrict__ W2, const float* __restrict__ b2) {
    GEMM_BODY(Hc,
              g_s1 + (size_t)(blockIdx.y * 128 + (threadIdx.x >> 1)) * Hc + ((threadIdx.x & 1) * 8),
              W2   + (size_t)(blockIdx.x * 128 + (threadIdx.x >> 1)) * Hc + ((threadIdx.x & 1) * 8),
              b2, g_h2, Dc)
}

// ---------------------------------------------------------------------------
// Exact pairwise f32->f64 sum of a float4 (each op exact in f64 until the
// final rounded adds; order-noise ~1e-16, irrelevant to the f32 result).
// ---------------------------------------------------------------------------
__device__ __forceinline__ double pair4(const float4& y) {
    return ((double)y.x + (double)y.y) + ((double)y.z + (double)y.w);
}
__device__ __forceinline__ double pair4sq(const float4& y, float mu) {
    const float dx = __fsub_rn(y.x, mu), dy = __fsub_rn(y.y, mu);
    const float dz = __fsub_rn(y.z, mu), dw = __fsub_rn(y.w, mu);
    return ((double)__fmul_rn(dx, dx) + (double)__fmul_rn(dy, dy)) +
           ((double)__fmul_rn(dz, dz) + (double)__fmul_rn(dw, dw));
}

// Elementwise LIF step, bit-exact op sequence (no contraction):
#define LIF_E(Y, G, B, V, S)                                                   \
    {                                                                          \
        const float yy = __fadd_rn(                                            \
            __fmul_rn(__fmul_rn(__fsub_rn((Y), mu), rs), (G)), (B));           \
        (V) = __fadd_rn((V), __fmul_rn(__fsub_rn(yy, (V)), 0.5f));             \
        (S) = ((V) >= 1.0f) ? 1.f : 0.f;                                       \
        (V) = __fmul_rn((V), __fsub_rn(1.0f, (S)));                            \
    }

// ---------------------------------------------------------------------------
// Layer-1 LN+LIF: one 192-thread block per (b,l) row (H=1536 = 192*8),
// membrane v in registers across T, cross-warp f64 reduce via smem.
// ---------------------------------------------------------------------------
__device__ __forceinline__ double block_reduce_d192(double a) {
    __shared__ double sh[8];
    const unsigned m = 0xffffffffu;
#pragma unroll
    for (int o = 16; o; o >>= 1) a += __shfl_xor_sync(m, a, o);
    const int lane = threadIdx.x & 31, w = threadIdx.x >> 5;
    __syncthreads();               // protect sh reuse across calls
    if (lane == 0) sh[w] = a;
    __syncthreads();
    if (w == 0) {
        double b = (lane < 6) ? sh[lane] : 0.0;
        b += __shfl_xor_sync(m, b, 4);
        b += __shfl_xor_sync(m, b, 2);
        b += __shfl_xor_sync(m, b, 1);
        if (lane == 0) sh[0] = b;
    }
    __syncthreads();
    return sh[0];
}

__global__ __launch_bounds__(192) void ln_lif1_kernel(
    const float* __restrict__ src, const float* __restrict__ gamma,
    const float* __restrict__ beta, float* __restrict__ dst) {
    const int bl = blockIdx.x;               // (b,l)
    const int bI = bl / Lc, l = bl % Lc;
    const int c0 = threadIdx.x * 4;
    const int c1 = c0 + 768;

    const float4 gg0 = *(const float4*)(gamma + c0);
    const float4 gg1 = *(const float4*)(gamma + c1);
    const float4 bb0 = *(const float4*)(beta + c0);
    const float4 bb1 = *(const float4*)(beta + c1);
    float4 v0 = make_float4(0.f, 0.f, 0.f, 0.f);
    float4 v1 = make_float4(0.f, 0.f, 0.f, 0.f);

    const int rbase = bI * Lc + l;
#pragma unroll
    for (int t = 0; t < Tc; t++) {
        const int r = t * (Bc * Lc) + rbase;
        const float* p = src + (size_t)r * Hc;
        const float4 y0 = *(const float4*)(p + c0);
        const float4 y1 = *(const float4*)(p + c1);

        const double s = block_reduce_d192(pair4(y0) + pair4(y1));
        const float mu = (float)(s / (double)Hc);

        const double s2 = block_reduce_d192(pair4sq(y0, mu) + pair4sq(y1, mu));
        const float var = (float)(s2 / (double)Hc);
        const float rs = __fdiv_rn(1.0f, __fsqrt_rn(__fadd_rn(var, 1e-5f)));

        float4 sp0, sp1;
        LIF_E(y0.x, gg0.x, bb0.x, v0.x, sp0.x)
        LIF_E(y0.y, gg0.y, bb0.y, v0.y, sp0.y)
        LIF_E(y0.z, gg0.z, bb0.z, v0.z, sp0.z)
        LIF_E(y0.w, gg0.w, bb0.w, v0.w, sp0.w)
        LIF_E(y1.x, gg1.x, bb1.x, v1.x, sp1.x)
        LIF_E(y1.y, gg1.y, bb1.y, v1.y, sp1.y)
        LIF_E(y1.z, gg1.z, bb1.z, v1.z, sp1.z)
        LIF_E(y1.w, gg1.w, bb1.w, v1.w, sp1.w)
        float* q = dst + (size_t)r * Hc;
        *(float4*)(q + c0) = sp0;
        *(float4*)(q + c1) = sp1;
    }
}

// ---------------------------------------------------------------------------
// Layer-2 LN+LIF -> final output [B,T,L,D]. Warp per (b,l) row (D=384=32*12),
// parallel f64 accumulators, no barriers.
// ---------------------------------------------------------------------------
__global__ __launch_bounds__(256) void ln_lif2_kernel(
    const float* __restrict__ src, const float* __restrict__ gamma,
    const float* __restrict__ beta, float* __restrict__ dst) {
    constexpr int J = Dc / 128;              // 3 float4 per lane
    const int bl = blockIdx.x * 8 + (threadIdx.x >> 5);
    const int lane = threadIdx.x & 31;
    const int bI = bl / Lc, l = bl % Lc;
    const unsigned msk = 0xffffffffu;

    float4 gg[J], bb[J], v[J];
#pragma unroll
    for (int j = 0; j < J; j++) {
        gg[j] = *(const float4*)(gamma + lane * 4 + j * 128);
        bb[j] = *(const float4*)(beta  + lane * 4 + j * 128);
        v[j] = make_float4(0.f, 0.f, 0.f, 0.f);
    }

    const int rbase = bI * Lc + l;
#pragma unroll
    for (int t = 0; t < Tc; t++) {
        const int r = t * (Bc * Lc) + rbase;
        const float* p = src + (size_t)r * Dc;
        float4 y[J];
#pragma unroll
        for (int j = 0; j < J; j++)
            y[j] = *(const float4*)(p + lane * 4 + j * 128);

        double s = (pair4(y[0]) + pair4(y[1])) + pair4(y[2]);
#pragma unroll
        for (int o = 16; o; o >>= 1) s += __shfl_xor_sync(msk, s, o);
        const float mu = (float)(s / (double)Dc);

        double s2 = (pair4sq(y[0], mu) + pair4sq(y[1], mu)) + pair4sq(y[2], mu);
#pragma unroll
        for (int o = 16; o; o >>= 1) s2 += __shfl_xor_sync(msk, s2, o);
        const float var = (float)(s2 / (double)Dc);
        const float rs = __fdiv_rn(1.0f, __fsqrt_rn(__fadd_rn(var, 1e-5f)));

        float* q = dst + (size_t)((bI * Tc + t) * Lc + l) * Dc;
#pragma unroll
        for (int j = 0; j < J; j++) {
            float4 sp;
            LIF_E(y[j].x, gg[j].x, bb[j].x, v[j].x, sp.x)
            LIF_E(y[j].y, gg[j].y, bb[j].y, v[j].y, sp.y)
            LIF_E(y[j].z, gg[j].z, bb[j].z, v[j].z, sp.z)
            LIF_E(y[j].w, gg[j].w, bb[j].w, v[j].w, sp.w)
            *(float4*)(q + lane * 4 + j * 128) = sp;
        }
    }
}

// ---------------------------------------------------------------------------
extern "C" void kernel_launch(void* const* d_in, const int* in_sizes, int n_in,
                              void* d_out, int out_size) {
    const float* x   = (const float*)d_in[0];
    const float* W1  = (const float*)d_in[1];
    const float* b1  = (const float*)d_in[2];
    const float* g1  = (const float*)d_in[3];
    const float* be1 = (const float*)d_in[4];
    const float* W2  = (const float*)d_in[5];
    const float* b2  = (const float*)d_in[6];
    const float* g2  = (const float*)d_in[7];
    const float* be2 = (const float*)d_in[8];
    float* out = (float*)d_out;

    float *h1, *s1, *h2;
    cudaGetSymbolAddress((void**)&h1, g_h1);
    cudaGetSymbolAddress((void**)&s1, g_s1);
    cudaGetSymbolAddress((void**)&h2, g_h2);

    gemm1_kernel<<<dim3(Hc / 128, Mrows / 128), 256>>>(x, W1, b1);
    ln_lif1_kernel<<<Bc * Lc, 192>>>(h1, g1, be1, s1);
    gemm2_kernel<<<dim3(Dc / 128, Mrows / 128), 256>>>(W2, b2);
    ln_lif2_kernel<<<(Bc * Lc) / 8, 256>>>(h2, g2, be2, out);
}